// round 5
// baseline (speedup 1.0000x reference)
#include <cuda_runtime.h>

// Fixed problem geometry (inputs are fixed by setup_inputs):
//   feats_r (3,1,64,48,84), feats_t (1,64,48,84), quantized_r (3,1,32,192,336)
//   gaps=[16,15,14] -> nsearch=1 (ref0, dilation 2), refs 1,2 plain dil-1
#define H   48
#define W   84
#define HW  4032
#define C   64
#define CQ  32
#define SRC_HW (192*336)   // 64512

// ---------------- scratch (device globals; no allocation) ----------------
__device__ float g_tT[HW*C];            // t, HWC layout: [(y*84+x)*64 + c]
__device__ float g_rT[3][HW*C];         // refs, HWC
__device__ float g_qrT[3][HW*CQ];       // subsampled quantized refs, HWC (32 ch)
__device__ float g_part[6][HW][4];      // per dy-group online-softmax partials (m,s,sy,sx)
__device__ float g_off[HW][2];          // off_y, off_x
__device__ float g_logits12[338*HW];    // logits for refs 1,2: [n12][pix]

// ---------------- K1: layout transforms ----------------
__global__ void prep_kernel(const float* __restrict__ fr,
                            const float* __restrict__ ft,
                            const float* __restrict__ qz) {
    int stride = gridDim.x * blockDim.x;
    int tid0 = blockIdx.x * blockDim.x + threadIdx.x;
    // t + 3 refs -> HWC  (output-coalesced; reads hit L1 via line reuse)
    for (int idx = tid0; idx < 4 * HW * C; idx += stride) {
        int a = idx / (HW * C);
        int j = idx - a * (HW * C);
        int pix = j >> 6;
        int c = j & 63;
        float v;
        if (a == 0) v = ft[c * HW + pix];
        else        v = fr[(a - 1) * (C * HW) + c * HW + pix];
        if (a == 0) g_tT[j] = v;
        else        g_rT[a - 1][j] = v;
    }
    // quantized refs: subsample ::4,::4 and go HWC
    for (int idx = tid0; idx < 3 * HW * CQ; idx += stride) {
        int a = idx / (HW * CQ);
        int j = idx - a * (HW * CQ);
        int pix = j >> 5;
        int c = j & 31;
        int y = pix / W;
        int x = pix - y * W;
        g_qrT[a][j] = qz[a * (CQ * SRC_HW) + c * SRC_HW + (4 * y) * 336 + 4 * x];
    }
}

// ---------------- K2: MP=25 dil=2 correlation -> online softmax moments ----------------
// grid (48, 6): block = (row y, dy-group g). blockDim 336 = 84 px * 4 q'-subs.
__global__ __launch_bounds__(336, 2) void offs_part_kernel() {
    int y = blockIdx.x;
    int g = blockIdx.y;
    int tid = threadIdx.x;
    int x = tid % 84;
    int sub = tid / 84;          // 0..3
    __shared__ float rs[C * W];  // c-major: rs[c*84 + xx]
    __shared__ float psh[4][84][4];

    float4 tr[16];
    {
        const float4* tp = reinterpret_cast<const float4*>(g_tT + (y * W + x) * C);
#pragma unroll
        for (int k = 0; k < 16; k++) tr[k] = tp[k];
    }

    float m = -1e30f, s = 0.f, sy = 0.f, sx = 0.f;

    for (int pp = g - 12; pp <= 12; pp += 6) {
        int yy = y + 2 * pp;
        bool rowok = (yy >= 0) && (yy < H);
        __syncthreads();
        if (rowok) {
            const float4* rp = reinterpret_cast<const float4*>(g_rT[0] + yy * (W * C));
            // 84*16 float4 = 1344; 336 threads -> 4 each; coalesced reads, c-major STS
            for (int i = tid; i < W * 16; i += 336) {
                float4 v = rp[i];
                int xx = i >> 4;
                int c4 = (i & 15) << 2;
                rs[(c4 + 0) * W + xx] = v.x;
                rs[(c4 + 1) * W + xx] = v.y;
                rs[(c4 + 2) * W + xx] = v.z;
                rs[(c4 + 3) * W + xx] = v.w;
            }
        }
        __syncthreads();
        for (int qq = sub - 12; qq <= 12; qq += 4) {
            int xx = x + 2 * qq;
            float logit = 0.f;
            if (rowok && xx >= 0 && xx < W) {
                const float* rc = rs + xx;
#pragma unroll
                for (int k = 0; k < 16; k++) {
                    logit += tr[k].x * rc[(4 * k + 0) * W];
                    logit += tr[k].y * rc[(4 * k + 1) * W];
                    logit += tr[k].z * rc[(4 * k + 2) * W];
                    logit += tr[k].w * rc[(4 * k + 3) * W];
                }
            }
            float fpp = (float)pp, fqq = (float)qq;
            if (logit > m) {
                float sc = __expf(m - logit);
                s = s * sc + 1.f;
                sy = sy * sc + fpp;
                sx = sx * sc + fqq;
                m = logit;
            } else {
                float e = __expf(logit - m);
                s += e;
                sy += e * fpp;
                sx += e * fqq;
            }
        }
    }
    __syncthreads();
    psh[sub][x][0] = m; psh[sub][x][1] = s; psh[sub][x][2] = sy; psh[sub][x][3] = sx;
    __syncthreads();
    if (sub == 0) {
        float M = m, S = s, SY = sy, SX = sx;
#pragma unroll
        for (int u = 1; u < 4; u++) {
            float m2 = psh[u][x][0], s2 = psh[u][x][1], sy2 = psh[u][x][2], sx2 = psh[u][x][3];
            if (m2 > M) {
                float e = __expf(M - m2);
                S = S * e + s2; SY = SY * e + sy2; SX = SX * e + sx2; M = m2;
            } else {
                float e = __expf(m2 - M);
                S += s2 * e; SY += sy2 * e; SX += sx2 * e;
            }
        }
        int pix = y * W + x;
        g_part[g][pix][0] = M; g_part[g][pix][1] = S;
        g_part[g][pix][2] = SY; g_part[g][pix][3] = SX;
    }
}

// ---------------- K3: merge partials -> offsets ----------------
__global__ void offs_merge_kernel() {
    int pix = blockIdx.x * blockDim.x + threadIdx.x;
    if (pix >= HW) return;
    float M = -1e30f, S = 0.f, SY = 0.f, SX = 0.f;
#pragma unroll
    for (int g = 0; g < 6; g++) {
        float m2 = g_part[g][pix][0], s2 = g_part[g][pix][1];
        float sy2 = g_part[g][pix][2], sx2 = g_part[g][pix][3];
        if (m2 > M) {
            float e = __expf(M - m2);
            S = S * e + s2; SY = SY * e + sy2; SX = SX * e + sx2; M = m2;
        } else {
            float e = __expf(m2 - M);
            S += s2 * e; SY += sy2 * e; SX += sx2 * e;
        }
    }
    float inv = 1.f / S;
    g_off[pix][0] = 2.f * SY * inv;   // off_y = d * E[p-12], d=2
    g_off[pix][1] = 2.f * SX * inv;   // off_x
}

// ---------------- K4: dil-1 correlations for refs 1,2 -> logits ----------------
// grid (13, 48, 2): (p-offset a, row y, ref-1). blockDim 336.
__global__ __launch_bounds__(336, 2) void logits12_kernel() {
    int a = blockIdx.x;            // 0..12
    int y = blockIdx.y;
    int ref = blockIdx.z + 1;      // 1..2
    int tid = threadIdx.x;
    int x = tid % 84;
    int sub = tid / 84;
    __shared__ float rs[C * W];

    int yy = y + a - 6;
    bool rowok = (yy >= 0) && (yy < H);

    float4 tr[16];
    {
        const float4* tp = reinterpret_cast<const float4*>(g_tT + (y * W + x) * C);
#pragma unroll
        for (int k = 0; k < 16; k++) tr[k] = tp[k];
    }

    if (rowok) {
        const float4* rp = reinterpret_cast<const float4*>(g_rT[ref] + yy * (W * C));
        for (int i = tid; i < W * 16; i += 336) {
            float4 v = rp[i];
            int xx = i >> 4;
            int c4 = (i & 15) << 2;
            rs[(c4 + 0) * W + xx] = v.x;
            rs[(c4 + 1) * W + xx] = v.y;
            rs[(c4 + 2) * W + xx] = v.z;
            rs[(c4 + 3) * W + xx] = v.w;
        }
    }
    __syncthreads();

    int pix = y * W + x;
    for (int b = sub; b < 13; b += 4) {
        int xx = x + b - 6;
        float logit = 0.f;
        if (rowok && xx >= 0 && xx < W) {
            const float* rc = rs + xx;
#pragma unroll
            for (int k = 0; k < 16; k++) {
                logit += tr[k].x * rc[(4 * k + 0) * W];
                logit += tr[k].y * rc[(4 * k + 1) * W];
                logit += tr[k].z * rc[(4 * k + 2) * W];
                logit += tr[k].w * rc[(4 * k + 3) * W];
            }
        }
        int n12 = (ref - 1) * 169 + a * 13 + b;
        g_logits12[n12 * HW + pix] = logit;   // coalesced across x
    }
}

// ---------------- K5: fused bilinear corr (ref0) + softmax(507) + output ----------------
// grid 4032 (one pixel per block), blockDim 256.
__global__ __launch_bounds__(256) void final_kernel(float* __restrict__ out) {
    int pix = blockIdx.x;
    int y = pix / W;
    int x = pix - y * W;
    int tid = threadIdx.x;

    __shared__ float tsh[C];
    __shared__ float lsh[507];
    __shared__ float Dsh[196];
    __shared__ float W0[196];
    __shared__ float red[8];
    __shared__ float oacc[8][32];

    if (tid < C) tsh[tid] = g_tT[pix * C + tid];

    float offy = g_off[pix][0];
    float offx = g_off[pix][1];
    float Yf = (float)y + offy;
    float Xf = (float)x + offx;
    float fYf = floorf(Yf), fXf = floorf(Xf);
    int fy = (int)fYf, fx = (int)fXf;
    float wy = Yf - fYf, wx = Xf - fXf;
    float c00 = (1.f - wy) * (1.f - wx);
    float c01 = (1.f - wy) * wx;
    float c10 = wy * (1.f - wx);
    float c11 = wy * wx;
    __syncthreads();

    // 14x14 integer-grid dot field D[a][b] = <t, r0[fy+a-6, fx+b-6]>
    for (int d0 = tid; d0 < 196; d0 += 256) {
        int aa = d0 / 14, bb = d0 - aa * 14;
        int ry = fy + aa - 6, rx = fx + bb - 6;
        float v = 0.f;
        if (ry >= 0 && ry < H && rx >= 0 && rx < W) {
            const float4* rp = reinterpret_cast<const float4*>(g_rT[0] + (ry * W + rx) * C);
            const float4* tp = reinterpret_cast<const float4*>(tsh);
#pragma unroll
            for (int k = 0; k < 16; k++) {
                float4 r4 = rp[k];
                float4 t4 = tp[k];
                v += r4.x * t4.x + r4.y * t4.y + r4.z * t4.z + r4.w * t4.w;
            }
        }
        Dsh[d0] = v;
    }
    __syncthreads();

    // ref0 logits from shared bilinear fractions
    for (int n = tid; n < 169; n += 256) {
        int p = n / 13, q = n - p * 13;
        lsh[n] = c00 * Dsh[p * 14 + q] + c01 * Dsh[p * 14 + q + 1]
               + c10 * Dsh[(p + 1) * 14 + q] + c11 * Dsh[(p + 1) * 14 + q + 1];
    }
    for (int n = tid; n < 338; n += 256) {
        lsh[169 + n] = g_logits12[n * HW + pix];
    }
    __syncthreads();

    // block softmax over 507 logits
    float lm = -1e30f;
    for (int n = tid; n < 507; n += 256) lm = fmaxf(lm, lsh[n]);
#pragma unroll
    for (int o = 16; o; o >>= 1) lm = fmaxf(lm, __shfl_xor_sync(0xffffffffu, lm, o));
    if ((tid & 31) == 0) red[tid >> 5] = lm;
    __syncthreads();
    float M = red[0];
#pragma unroll
    for (int i = 1; i < 8; i++) M = fmaxf(M, red[i]);
    __syncthreads();

    float ls = 0.f;
    for (int n = tid; n < 507; n += 256) {
        float e = __expf(lsh[n] - M);
        lsh[n] = e;            // store unnormalized weight
        ls += e;
    }
#pragma unroll
    for (int o = 16; o; o >>= 1) ls += __shfl_xor_sync(0xffffffffu, ls, o);
    __syncthreads();
    if ((tid & 31) == 0) red[tid >> 5] = ls;
    __syncthreads();
    float S = 0.f;
#pragma unroll
    for (int i = 0; i < 8; i++) S += red[i];
    float invS = 1.f / S;

    // combined integer-grid weights for ref0 output gather
    for (int d0 = tid; d0 < 196; d0 += 256) {
        int aa = d0 / 14, bb = d0 - aa * 14;
        float w00 = (aa < 13 && bb < 13) ? lsh[aa * 13 + bb] : 0.f;
        float w01 = (aa < 13 && bb >= 1) ? lsh[aa * 13 + bb - 1] : 0.f;
        float w10 = (aa >= 1 && bb < 13) ? lsh[(aa - 1) * 13 + bb] : 0.f;
        float w11 = (aa >= 1 && bb >= 1) ? lsh[(aa - 1) * 13 + bb - 1] : 0.f;
        W0[d0] = c00 * w00 + c01 * w01 + c10 * w10 + c11 * w11;
    }
    __syncthreads();

    // weighted gather of quantized refs: 534 samples x 32 channels
    float acc[32];
#pragma unroll
    for (int cc = 0; cc < 32; cc++) acc[cc] = 0.f;

    for (int sidx = tid; sidx < 534; sidx += 256) {
        float wgt;
        int ry, rx;
        const float* src;
        if (sidx < 196) {
            int aa = sidx / 14, bb = sidx - aa * 14;
            wgt = W0[sidx];
            ry = fy + aa - 6; rx = fx + bb - 6;
            src = g_qrT[0];
        } else if (sidx < 365) {
            int n = sidx - 196;
            int p = n / 13, q = n - p * 13;
            wgt = lsh[169 + n];
            ry = y + p - 6; rx = x + q - 6;
            src = g_qrT[1];
        } else {
            int n = sidx - 365;
            int p = n / 13, q = n - p * 13;
            wgt = lsh[338 + n];
            ry = y + p - 6; rx = x + q - 6;
            src = g_qrT[2];
        }
        if (ry >= 0 && ry < H && rx >= 0 && rx < W && wgt != 0.f) {
            const float4* qp = reinterpret_cast<const float4*>(src + (ry * W + rx) * CQ);
#pragma unroll
            for (int k = 0; k < 8; k++) {
                float4 v = qp[k];
                acc[4 * k + 0] += wgt * v.x;
                acc[4 * k + 1] += wgt * v.y;
                acc[4 * k + 2] += wgt * v.z;
                acc[4 * k + 3] += wgt * v.w;
            }
        }
    }

    // reduce 32-channel accumulators across block
#pragma unroll
    for (int cc = 0; cc < 32; cc++) {
#pragma unroll
        for (int o = 16; o; o >>= 1)
            acc[cc] += __shfl_xor_sync(0xffffffffu, acc[cc], o);
    }
    if ((tid & 31) == 0) {
        int wrp = tid >> 5;
#pragma unroll
        for (int cc = 0; cc < 32; cc++) oacc[wrp][cc] = acc[cc];
    }
    __syncthreads();
    if (tid < 32) {
        float t = 0.f;
#pragma unroll
        for (int wrp = 0; wrp < 8; wrp++) t += oacc[wrp][tid];
        out[tid * HW + pix] = t * invS;   // out[c, y, x]
    }
}

// ---------------- launch ----------------
extern "C" void kernel_launch(void* const* d_in, const int* in_sizes, int n_in,
                              void* d_out, int out_size) {
    const float* fr = (const float*)d_in[0];   // feats_r (3,1,64,48,84)
    const float* ft = (const float*)d_in[1];   // feats_t (1,64,48,84)
    const float* qz = (const float*)d_in[2];   // quantized_r (3,1,32,192,336)
    float* out = (float*)d_out;                // (1,32,48,84) f32

    prep_kernel<<<512, 256>>>(fr, ft, qz);
    offs_part_kernel<<<dim3(48, 6), 336>>>();
    offs_merge_kernel<<<16, 256>>>();
    logits12_kernel<<<dim3(13, 48, 2), 336>>>();
    final_kernel<<<HW, 256>>>(out);
}

// round 8
// speedup vs baseline: 1.1413x; 1.1413x over previous
#include <cuda_runtime.h>

// Fixed geometry: feats_r (3,1,64,48,84), feats_t (1,64,48,84),
// quantized_r (3,1,32,192,336); gaps=[16,15,14] -> nsearch=1 (ref0 dil=2),
// refs 1,2 plain dil-1, P=13 (N=169), MP=25.
#define H   48
#define W   84
#define HW  4032
#define C   64
#define CQ  32
#define SRC_HW (192*336)

// ---------------- scratch ----------------
__device__ float g_tT[HW*C];            // t, HWC
__device__ float g_rT[3][HW*C];         // refs, HWC
__device__ float g_qrT[3][HW*CQ];       // subsampled quantized refs, HWC
__device__ float g_part[25][HW][4];     // per-pp online-softmax partials (m,s,sy,sx)
__device__ float g_off[HW][2];          // off_y, off_x
__device__ float g_logits12[HW*338];    // refs 1,2 logits, PIXEL-major: [pix*338 + n]

// ---------------- K1a: feature transpose (64 x 4032 -> HWC) ----------------
__global__ void prep_feats_kernel(const float* __restrict__ fr,
                                  const float* __restrict__ ft) {
    __shared__ float tile[32][33];
    int t = blockIdx.z;                          // 0 = ft, 1..3 = refs
    const float* src = (t == 0) ? ft : (fr + (t - 1) * (C * HW));
    float* dst = (t == 0) ? g_tT : g_rT[t - 1];
    int pix0 = blockIdx.x * 32;
    int c0 = blockIdx.y * 32;
    for (int r = threadIdx.y; r < 32; r += 8)
        tile[r][threadIdx.x] = src[(c0 + r) * HW + pix0 + threadIdx.x];
    __syncthreads();
    for (int r = threadIdx.y; r < 32; r += 8)
        dst[(pix0 + r) * C + c0 + threadIdx.x] = tile[threadIdx.x][r];
}

// ---------------- K1b: quantized ref subsample -> HWC ----------------
__global__ void prep_qr_kernel(const float* __restrict__ qz) {
    int stride = gridDim.x * blockDim.x;
    for (int idx = blockIdx.x * blockDim.x + threadIdx.x;
         idx < 3 * HW * CQ; idx += stride) {
        int a = idx / (HW * CQ);
        int j = idx - a * (HW * CQ);
        int pix = j >> 5;
        int c = j & 31;
        int y = pix / W;
        int x = pix - y * W;
        g_qrT[a][j] = qz[a * (CQ * SRC_HW) + c * SRC_HW + (4 * y) * 336 + 4 * x];
    }
}

// ---------------- K2: MP=25 dil=2 correlation, register-tiled ----------------
// grid (48, 25): (row y, pp+12). 96 threads; 84 jobs = 21 xt * 4 qt.
// Thread: 4 x-pixels (jx) * 8 q-offsets (jq), qi = 8*qt+jq (<25).
// shared idx for (jx,jq): (4xt+16qt) + jx + 2jq  -> 20-float aligned window.
#define RSW2 148   // rs row width: max rbase(128)+20 <= 148, 4-aligned
__global__ __launch_bounds__(96) void offs2_kernel() {
    int y = blockIdx.x;
    int gp = blockIdx.y;          // 0..24
    int pp = gp - 12;
    int yy = y + 2 * pp;
    bool rowok = (yy >= 0) && (yy < H);
    int tid = threadIdx.x;

    __shared__ float ts[32 * 84];       // [k][x]
    __shared__ float rs[32 * RSW2];     // [k][xx+24], zero-padded borders

    int jt = (tid < 84) ? tid : 0;      // clamp spare threads to a safe job
    int xt = jt >> 2;                   // 0..20
    int qt = jt & 3;                    // 0..3

    float acc[4][8];
#pragma unroll
    for (int i = 0; i < 4; i++)
#pragma unroll
        for (int j = 0; j < 8; j++) acc[i][j] = 0.f;

    const float4* tp = reinterpret_cast<const float4*>(g_tT + y * (W * C));
    const float4* rp = reinterpret_cast<const float4*>(g_rT[0] + yy * (W * C));

    for (int kc = 0; kc < 2; kc++) {
        // zero rs borders: cols [0,24) U [108,148)  -> 64 cols per k-row
        for (int i = tid; i < 32 * 64; i += 96) {
            int kk = i >> 6, j = i & 63;
            int col = (j < 24) ? j : (84 + j);   // 24..63 -> 108..147
            rs[kk * RSW2 + col] = 0.f;
        }
        // fill ts chunk (channels kc*32 .. +32)
        for (int i = tid; i < 84 * 8; i += 96) {
            int x = i >> 3, f = i & 7;
            float4 v = tp[x * 16 + kc * 8 + f];
            int c4 = f << 2;
            ts[(c4 + 0) * 84 + x] = v.x;
            ts[(c4 + 1) * 84 + x] = v.y;
            ts[(c4 + 2) * 84 + x] = v.z;
            ts[(c4 + 3) * 84 + x] = v.w;
        }
        // fill rs interior
        if (rowok) {
            for (int i = tid; i < 84 * 8; i += 96) {
                int x = i >> 3, f = i & 7;
                float4 v = rp[x * 16 + kc * 8 + f];
                int c4 = f << 2;
                rs[(c4 + 0) * RSW2 + 24 + x] = v.x;
                rs[(c4 + 1) * RSW2 + 24 + x] = v.y;
                rs[(c4 + 2) * RSW2 + 24 + x] = v.z;
                rs[(c4 + 3) * RSW2 + 24 + x] = v.w;
            }
        } else {
            for (int i = tid; i < 32 * 84; i += 96) {
                int kk = i / 84, x = i - kk * 84;
                rs[kk * RSW2 + 24 + x] = 0.f;
            }
        }
        __syncthreads();

        int tbase = 4 * xt;
        int rbase = 4 * xt + 16 * qt;   // sh idx = rbase + jx + 2jq
#pragma unroll 4
        for (int k = 0; k < 32; k++) {
            float4 tq = *reinterpret_cast<const float4*>(ts + k * 84 + tbase);
            const float4* rr = reinterpret_cast<const float4*>(rs + k * RSW2 + rbase);
            float4 r0 = rr[0], r1 = rr[1], r2 = rr[2], r3 = rr[3], r4 = rr[4];
            float rv[20] = {r0.x,r0.y,r0.z,r0.w, r1.x,r1.y,r1.z,r1.w,
                            r2.x,r2.y,r2.z,r2.w, r3.x,r3.y,r3.z,r3.w,
                            r4.x,r4.y,r4.z,r4.w};
            float tv[4] = {tq.x, tq.y, tq.z, tq.w};
#pragma unroll
            for (int jx = 0; jx < 4; jx++)
#pragma unroll
                for (int jq = 0; jq < 8; jq++)
                    acc[jx][jq] += tv[jx] * rv[jx + 2 * jq];
        }
        __syncthreads();
    }

    // per-jx online softmax over valid qi, then shfl-merge across qt (4 lanes)
    float fpp = (float)pp;
    float m[4], s[4], sy[4], sx[4];
#pragma unroll
    for (int jx = 0; jx < 4; jx++) {
        m[jx] = -1e30f; s[jx] = 0.f; sy[jx] = 0.f; sx[jx] = 0.f;
#pragma unroll
        for (int jq = 0; jq < 8; jq++) {
            int qi = 8 * qt + jq;
            if (qi < 25) {
                float logit = acc[jx][jq];
                float fqq = (float)(qi - 12);
                if (logit > m[jx]) {
                    float e = __expf(m[jx] - logit);
                    s[jx] = s[jx] * e + 1.f;
                    sy[jx] = sy[jx] * e + fpp;
                    sx[jx] = sx[jx] * e + fqq;
                    m[jx] = logit;
                } else {
                    float e = __expf(logit - m[jx]);
                    s[jx] += e; sy[jx] += e * fpp; sx[jx] += e * fqq;
                }
            }
        }
    }
#pragma unroll
    for (int o = 1; o <= 2; o <<= 1) {
#pragma unroll
        for (int jx = 0; jx < 4; jx++) {
            float m2 = __shfl_xor_sync(0xffffffffu, m[jx], o);
            float s2 = __shfl_xor_sync(0xffffffffu, s[jx], o);
            float sy2 = __shfl_xor_sync(0xffffffffu, sy[jx], o);
            float sx2 = __shfl_xor_sync(0xffffffffu, sx[jx], o);
            if (m2 > m[jx]) {
                float e = __expf(m[jx] - m2);
                s[jx] = s[jx] * e + s2; sy[jx] = sy[jx] * e + sy2;
                sx[jx] = sx[jx] * e + sx2; m[jx] = m2;
            } else {
                float e = __expf(m2 - m[jx]);
                s[jx] += s2 * e; sy[jx] += sy2 * e; sx[jx] += sx2 * e;
            }
        }
    }
    if (tid < 84 && qt == 0) {
#pragma unroll
        for (int jx = 0; jx < 4; jx++) {
            int pix = y * W + 4 * xt + jx;
            g_part[gp][pix][0] = m[jx];
            g_part[gp][pix][1] = s[jx];
            g_part[gp][pix][2] = sy[jx];
            g_part[gp][pix][3] = sx[jx];
        }
    }
}

// ---------------- K3: merge 25 partials -> offsets ----------------
__global__ void offs_merge_kernel() {
    int pix = blockIdx.x * blockDim.x + threadIdx.x;
    if (pix >= HW) return;
    float M = -1e30f, S = 0.f, SY = 0.f, SX = 0.f;
    for (int g = 0; g < 25; g++) {
        float m2 = g_part[g][pix][0], s2 = g_part[g][pix][1];
        float sy2 = g_part[g][pix][2], sx2 = g_part[g][pix][3];
        if (m2 > M) {
            float e = __expf(M - m2);
            S = S * e + s2; SY = SY * e + sy2; SX = SX * e + sx2; M = m2;
        } else {
            float e = __expf(m2 - M);
            S += s2 * e; SY += sy2 * e; SX += sx2 * e;
        }
    }
    float inv = 1.f / S;
    g_off[pix][0] = 2.f * SY * inv;
    g_off[pix][1] = 2.f * SX * inv;
}

// ---------------- K4: dil-1 correlations refs 1,2, register-tiled ----------------
// grid (48, 7, 2): (row y, a-pair, ref-1). 168 threads = 2 ap * 21 xt * 4 bt.
// Thread: 4 x-pixels (jx) * 4 b-offsets (jb), b = 4*bt+jb (store if b<13).
// shared idx for (jx,jb): (4xt+4bt) + jx + jb + 2  -> 12-float aligned window.
#define RSW4 104   // rs row width: max rbase0(92)+12 <= 104, 4-aligned
__global__ __launch_bounds__(168) void logits12b_kernel() {
    int y = blockIdx.x;
    int a0 = blockIdx.y * 2;
    int ref = blockIdx.z + 1;
    int tid = threadIdx.x;

    __shared__ float ts[32 * 84];          // [k][x]
    __shared__ float rs[2][32 * RSW4];     // [ap][k][xx+8], zero-padded

    int ap = tid / 84;                     // 0..1
    int rem = tid - ap * 84;
    int xt = rem >> 2;                     // 0..20
    int bt = rem & 3;                      // 0..3

    float acc[4][4];
#pragma unroll
    for (int i = 0; i < 4; i++)
#pragma unroll
        for (int j = 0; j < 4; j++) acc[i][j] = 0.f;

    const float4* tp = reinterpret_cast<const float4*>(g_tT + y * (W * C));

    for (int kc = 0; kc < 2; kc++) {
        // ts chunk
        for (int i = tid; i < 84 * 8; i += 168) {
            int x = i >> 3, f = i & 7;
            float4 v = tp[x * 16 + kc * 8 + f];
            int c4 = f << 2;
            ts[(c4 + 0) * 84 + x] = v.x;
            ts[(c4 + 1) * 84 + x] = v.y;
            ts[(c4 + 2) * 84 + x] = v.z;
            ts[(c4 + 3) * 84 + x] = v.w;
        }
        // rs chunks for both a rows
        for (int aa = 0; aa < 2; aa++) {
            int yy = y + (a0 + aa) - 6;
            bool rowok = (yy >= 0) && (yy < H);
            if (rowok) {
                // zero borders: cols [0,8) U [92,104) -> 20 cols per k-row
                for (int i = tid; i < 32 * 20; i += 168) {
                    int kk = i / 20, j = i - kk * 20;
                    int col = (j < 8) ? j : (84 + j);  // 8..19 -> 92..103
                    rs[aa][kk * RSW4 + col] = 0.f;
                }
                const float4* rp = reinterpret_cast<const float4*>(g_rT[ref] + yy * (W * C));
                for (int i = tid; i < 84 * 8; i += 168) {
                    int x = i >> 3, f = i & 7;
                    float4 v = rp[x * 16 + kc * 8 + f];
                    int c4 = f << 2;
                    rs[aa][(c4 + 0) * RSW4 + 8 + x] = v.x;
                    rs[aa][(c4 + 1) * RSW4 + 8 + x] = v.y;
                    rs[aa][(c4 + 2) * RSW4 + 8 + x] = v.z;
                    rs[aa][(c4 + 3) * RSW4 + 8 + x] = v.w;
                }
            } else {
                for (int i = tid; i < 32 * RSW4; i += 168) rs[aa][i] = 0.f;
            }
        }
        __syncthreads();

        int tbase = 4 * xt;
        int rbase0 = 4 * xt + 4 * bt;     // sh idx = rbase0 + jx + jb + 2
        const float* rsa = rs[ap];
#pragma unroll 4
        for (int k = 0; k < 32; k++) {
            float4 tq = *reinterpret_cast<const float4*>(ts + k * 84 + tbase);
            const float4* rr = reinterpret_cast<const float4*>(rsa + k * RSW4 + rbase0);
            float4 r0 = rr[0], r1 = rr[1], r2 = rr[2];
            float rv[12] = {r0.x,r0.y,r0.z,r0.w, r1.x,r1.y,r1.z,r1.w,
                            r2.x,r2.y,r2.z,r2.w};
            float tv[4] = {tq.x, tq.y, tq.z, tq.w};
#pragma unroll
            for (int jx = 0; jx < 4; jx++)
#pragma unroll
                for (int jb = 0; jb < 4; jb++)
                    acc[jx][jb] += tv[jx] * rv[jx + jb + 2];
        }
        __syncthreads();
    }

    int a = a0 + ap;
    if (a < 13) {
#pragma unroll
        for (int jx = 0; jx < 4; jx++) {
            int pix = y * W + 4 * xt + jx;
#pragma unroll
            for (int jb = 0; jb < 4; jb++) {
                int b = 4 * bt + jb;
                if (b < 13)
                    g_logits12[pix * 338 + (ref - 1) * 169 + a * 13 + b] = acc[jx][jb];
            }
        }
    }
}

// ---------------- K5: fused bilinear corr (ref0) + softmax(507) + output ----------------
__global__ __launch_bounds__(256) void final2_kernel(float* __restrict__ out) {
    int pix = blockIdx.x;
    int y = pix / W;
    int x = pix - y * W;
    int tid = threadIdx.x;
    int wid = tid >> 5;
    int lane = tid & 31;

    __shared__ float lsh[507];
    __shared__ float Dsh[196];
    __shared__ float W0[196];
    __shared__ float red[8];
    __shared__ float oacc[8][32];
    __shared__ float offsh[2];

    if (tid == 0) { offsh[0] = g_off[pix][0]; offsh[1] = g_off[pix][1]; }
    float2 t2 = reinterpret_cast<const float2*>(g_tT + pix * C)[lane];
    __syncthreads();

    float Yf = (float)y + offsh[0];
    float Xf = (float)x + offsh[1];
    float fYf = floorf(Yf), fXf = floorf(Xf);
    int fy = (int)fYf, fx = (int)fXf;
    float wy = Yf - fYf, wx = Xf - fXf;
    float c00 = (1.f - wy) * (1.f - wx);
    float c01 = (1.f - wy) * wx;
    float c10 = wy * (1.f - wx);
    float c11 = wy * wx;

    // refs 1,2 logits (coalesced, pixel-major)
    for (int n = tid; n < 338; n += 256)
        lsh[169 + n] = g_logits12[pix * 338 + n];

    // 14x14 integer-grid dot field: warp-per-dot, lane = 2 channels
    for (int d = wid; d < 196; d += 8) {
        int aa = d / 14, bb = d - aa * 14;
        int ry = fy + aa - 6, rx = fx + bb - 6;
        float v = 0.f;
        if ((unsigned)ry < (unsigned)H && (unsigned)rx < (unsigned)W) {
            float2 r2 = reinterpret_cast<const float2*>(g_rT[0] + (ry * W + rx) * C)[lane];
            v = t2.x * r2.x + t2.y * r2.y;
#pragma unroll
            for (int o = 16; o; o >>= 1) v += __shfl_xor_sync(0xffffffffu, v, o);
        }
        if (lane == 0) Dsh[d] = v;
    }
    __syncthreads();

    // ref0 logits via shared bilinear fractions
    for (int n = tid; n < 169; n += 256) {
        int p = n / 13, q = n - p * 13;
        lsh[n] = c00 * Dsh[p * 14 + q] + c01 * Dsh[p * 14 + q + 1]
               + c10 * Dsh[(p + 1) * 14 + q] + c11 * Dsh[(p + 1) * 14 + q + 1];
    }
    __syncthreads();

    // block softmax over 507 logits
    float lm = -1e30f;
    for (int n = tid; n < 507; n += 256) lm = fmaxf(lm, lsh[n]);
#pragma unroll
    for (int o = 16; o; o >>= 1) lm = fmaxf(lm, __shfl_xor_sync(0xffffffffu, lm, o));
    if (lane == 0) red[wid] = lm;
    __syncthreads();
    float M = red[0];
#pragma unroll
    for (int i = 1; i < 8; i++) M = fmaxf(M, red[i]);
    __syncthreads();

    float ls = 0.f;
    for (int n = tid; n < 507; n += 256) {
        float e = __expf(lsh[n] - M);
        lsh[n] = e;
        ls += e;
    }
#pragma unroll
    for (int o = 16; o; o >>= 1) ls += __shfl_xor_sync(0xffffffffu, ls, o);
    if (lane == 0) red[wid] = ls;
    __syncthreads();
    float S = 0.f;
#pragma unroll
    for (int i = 0; i < 8; i++) S += red[i];
    float invS = 1.f / S;

    // combined integer-grid weights for ref0 output gather
    for (int d = tid; d < 196; d += 256) {
        int aa = d / 14, bb = d - aa * 14;
        float w00 = (aa < 13 && bb < 13) ? lsh[aa * 13 + bb] : 0.f;
        float w01 = (aa < 13 && bb >= 1) ? lsh[aa * 13 + bb - 1] : 0.f;
        float w10 = (aa >= 1 && bb < 13) ? lsh[(aa - 1) * 13 + bb] : 0.f;
        float w11 = (aa >= 1 && bb >= 1) ? lsh[(aa - 1) * 13 + bb - 1] : 0.f;
        W0[d] = c00 * w00 + c01 * w01 + c10 * w10 + c11 * w11;
    }
    __syncthreads();

    // gather: warp-per-sample, lane = channel, coalesced 128B loads
    float acc = 0.f;
    for (int s = wid; s < 534; s += 8) {
        float wgt;
        int ry, rx;
        const float* src;
        if (s < 196) {
            int aa = s / 14, bb = s - aa * 14;
            wgt = W0[s];
            ry = fy + aa - 6; rx = fx + bb - 6;
            src = g_qrT[0];
        } else if (s < 365) {
            int n = s - 196;
            int p = n / 13, q = n - p * 13;
            wgt = lsh[169 + n];
            ry = y + p - 6; rx = x + q - 6;
            src = g_qrT[1];
        } else {
            int n = s - 365;
            int p = n / 13, q = n - p * 13;
            wgt = lsh[338 + n];
            ry = y + p - 6; rx = x + q - 6;
            src = g_qrT[2];
        }
        if ((unsigned)ry < (unsigned)H && (unsigned)rx < (unsigned)W)
            acc += wgt * src[(ry * W + rx) * CQ + lane];
    }
    oacc[wid][lane] = acc;
    __syncthreads();
    if (tid < 32) {
        float t = 0.f;
#pragma unroll
        for (int wrp = 0; wrp < 8; wrp++) t += oacc[wrp][tid];
        out[tid * HW + pix] = t * invS;
    }
}

// ---------------- launch ----------------
extern "C" void kernel_launch(void* const* d_in, const int* in_sizes, int n_in,
                              void* d_out, int out_size) {
    const float* fr = (const float*)d_in[0];
    const float* ft = (const float*)d_in[1];
    const float* qz = (const float*)d_in[2];
    float* out = (float*)d_out;

    prep_feats_kernel<<<dim3(126, 2, 4), dim3(32, 8)>>>(fr, ft);
    prep_qr_kernel<<<256, 256>>>(qz);
    offs2_kernel<<<dim3(48, 25), 96>>>();
    offs_merge_kernel<<<16, 256>>>();
    logits12b_kernel<<<dim3(48, 7, 2), 168>>>();
    final2_kernel<<<HW, 256>>>(out);
}

// round 9
// speedup vs baseline: 1.2214x; 1.0702x over previous
#include <cuda_runtime.h>

// Fixed geometry: feats_r (3,1,64,48,84), feats_t (1,64,48,84),
// quantized_r (3,1,32,192,336); gaps=[16,15,14] -> nsearch=1 (ref0 dil=2),
// refs 1,2 plain dil-1, P=13 (N=169), MP=25.
#define H   48
#define W   84
#define HW  4032
#define C   64
#define CQ  32
#define SRC_HW (192*336)

// ---------------- scratch ----------------
__device__ float g_tT[HW*C];            // t, HWC
__device__ float g_rT[3][HW*C];         // refs, HWC
__device__ float g_qrT[3][HW*CQ];       // subsampled quantized refs, HWC
__device__ float g_part[25][HW][4];     // per-pp online-softmax partials (m,s,sy,sx)
__device__ float g_off[HW][2];          // off_y, off_x
__device__ float g_logits12[HW*338];    // refs 1,2 logits, PIXEL-major: [pix*338 + n]

// ---------------- K1a: feature transpose (64 x 4032 -> HWC) ----------------
__global__ void prep_feats_kernel(const float* __restrict__ fr,
                                  const float* __restrict__ ft) {
    __shared__ float tile[32][33];
    int t = blockIdx.z;                          // 0 = ft, 1..3 = refs
    const float* src = (t == 0) ? ft : (fr + (t - 1) * (C * HW));
    float* dst = (t == 0) ? g_tT : g_rT[t - 1];
    int pix0 = blockIdx.x * 32;
    int c0 = blockIdx.y * 32;
    for (int r = threadIdx.y; r < 32; r += 8)
        tile[r][threadIdx.x] = src[(c0 + r) * HW + pix0 + threadIdx.x];
    __syncthreads();
    for (int r = threadIdx.y; r < 32; r += 8)
        dst[(pix0 + r) * C + c0 + threadIdx.x] = tile[threadIdx.x][r];
}

// ---------------- K1b: quantized ref subsample -> HWC ----------------
__global__ void prep_qr_kernel(const float* __restrict__ qz) {
    int stride = gridDim.x * blockDim.x;
    for (int idx = blockIdx.x * blockDim.x + threadIdx.x;
         idx < 3 * HW * CQ; idx += stride) {
        int a = idx / (HW * CQ);
        int j = idx - a * (HW * CQ);
        int pix = j >> 5;
        int c = j & 31;
        int y = pix / W;
        int x = pix - y * W;
        g_qrT[a][j] = qz[a * (CQ * SRC_HW) + c * SRC_HW + (4 * y) * 336 + 4 * x];
    }
}

// ---------------- K2: MP=25 dil=2 correlation, register-tiled ----------------
// grid (48, 25): (row y, pp+12). 96 threads; 84 jobs = 21 xt * 4 qt.
// Thread: 4 x-pixels (jx) * 8 q-offsets (jq), qi = 8*qt+jq (<25).
// shared idx for (jx,jq): (4xt+16qt) + jx + 2jq  -> 20-float aligned window.
#define RSW2 148   // rs row width: max rbase(128)+20 <= 148, 4-aligned
__global__ __launch_bounds__(96) void offs2_kernel() {
    int y = blockIdx.x;
    int gp = blockIdx.y;          // 0..24
    int pp = gp - 12;
    int yy = y + 2 * pp;
    bool rowok = (yy >= 0) && (yy < H);
    int tid = threadIdx.x;

    __shared__ float ts[32 * 84];       // [k][x]
    __shared__ float rs[32 * RSW2];     // [k][xx+24], zero-padded borders

    int jt = (tid < 84) ? tid : 0;      // clamp spare threads to a safe job
    int xt = jt >> 2;                   // 0..20
    int qt = jt & 3;                    // 0..3

    float acc[4][8];
#pragma unroll
    for (int i = 0; i < 4; i++)
#pragma unroll
        for (int j = 0; j < 8; j++) acc[i][j] = 0.f;

    const float4* tp = reinterpret_cast<const float4*>(g_tT + y * (W * C));
    const float4* rp = reinterpret_cast<const float4*>(g_rT[0] + yy * (W * C));

    for (int kc = 0; kc < 2; kc++) {
        // zero rs borders: cols [0,24) U [108,148)  -> 64 cols per k-row
        for (int i = tid; i < 32 * 64; i += 96) {
            int kk = i >> 6, j = i & 63;
            int col = (j < 24) ? j : (84 + j);   // 24..63 -> 108..147
            rs[kk * RSW2 + col] = 0.f;
        }
        // fill ts chunk (channels kc*32 .. +32)
        for (int i = tid; i < 84 * 8; i += 96) {
            int x = i >> 3, f = i & 7;
            float4 v = tp[x * 16 + kc * 8 + f];
            int c4 = f << 2;
            ts[(c4 + 0) * 84 + x] = v.x;
            ts[(c4 + 1) * 84 + x] = v.y;
            ts[(c4 + 2) * 84 + x] = v.z;
            ts[(c4 + 3) * 84 + x] = v.w;
        }
        // fill rs interior
        if (rowok) {
            for (int i = tid; i < 84 * 8; i += 96) {
                int x = i >> 3, f = i & 7;
                float4 v = rp[x * 16 + kc * 8 + f];
                int c4 = f << 2;
                rs[(c4 + 0) * RSW2 + 24 + x] = v.x;
                rs[(c4 + 1) * RSW2 + 24 + x] = v.y;
                rs[(c4 + 2) * RSW2 + 24 + x] = v.z;
                rs[(c4 + 3) * RSW2 + 24 + x] = v.w;
            }
        } else {
            for (int i = tid; i < 32 * 84; i += 96) {
                int kk = i / 84, x = i - kk * 84;
                rs[kk * RSW2 + 24 + x] = 0.f;
            }
        }
        __syncthreads();

        int tbase = 4 * xt;
        int rbase = 4 * xt + 16 * qt;   // sh idx = rbase + jx + 2jq
#pragma unroll 4
        for (int k = 0; k < 32; k++) {
            float4 tq = *reinterpret_cast<const float4*>(ts + k * 84 + tbase);
            const float4* rr = reinterpret_cast<const float4*>(rs + k * RSW2 + rbase);
            float4 r0 = rr[0], r1 = rr[1], r2 = rr[2], r3 = rr[3], r4 = rr[4];
            float rv[20] = {r0.x,r0.y,r0.z,r0.w, r1.x,r1.y,r1.z,r1.w,
                            r2.x,r2.y,r2.z,r2.w, r3.x,r3.y,r3.z,r3.w,
                            r4.x,r4.y,r4.z,r4.w};
            float tv[4] = {tq.x, tq.y, tq.z, tq.w};
#pragma unroll
            for (int jx = 0; jx < 4; jx++)
#pragma unroll
                for (int jq = 0; jq < 8; jq++)
                    acc[jx][jq] += tv[jx] * rv[jx + 2 * jq];
        }
        __syncthreads();
    }

    // per-jx online softmax over valid qi, then shfl-merge across qt (4 lanes)
    float fpp = (float)pp;
    float m[4], s[4], sy[4], sx[4];
#pragma unroll
    for (int jx = 0; jx < 4; jx++) {
        m[jx] = -1e30f; s[jx] = 0.f; sy[jx] = 0.f; sx[jx] = 0.f;
#pragma unroll
        for (int jq = 0; jq < 8; jq++) {
            int qi = 8 * qt + jq;
            if (qi < 25) {
                float logit = acc[jx][jq];
                float fqq = (float)(qi - 12);
                if (logit > m[jx]) {
                    float e = __expf(m[jx] - logit);
                    s[jx] = s[jx] * e + 1.f;
                    sy[jx] = sy[jx] * e + fpp;
                    sx[jx] = sx[jx] * e + fqq;
                    m[jx] = logit;
                } else {
                    float e = __expf(logit - m[jx]);
                    s[jx] += e; sy[jx] += e * fpp; sx[jx] += e * fqq;
                }
            }
        }
    }
#pragma unroll
    for (int o = 1; o <= 2; o <<= 1) {
#pragma unroll
        for (int jx = 0; jx < 4; jx++) {
            float m2 = __shfl_xor_sync(0xffffffffu, m[jx], o);
            float s2 = __shfl_xor_sync(0xffffffffu, s[jx], o);
            float sy2 = __shfl_xor_sync(0xffffffffu, sy[jx], o);
            float sx2 = __shfl_xor_sync(0xffffffffu, sx[jx], o);
            if (m2 > m[jx]) {
                float e = __expf(m[jx] - m2);
                s[jx] = s[jx] * e + s2; sy[jx] = sy[jx] * e + sy2;
                sx[jx] = sx[jx] * e + sx2; m[jx] = m2;
            } else {
                float e = __expf(m2 - m[jx]);
                s[jx] += s2 * e; sy[jx] += sy2 * e; sx[jx] += sx2 * e;
            }
        }
    }
    if (tid < 84 && qt == 0) {
#pragma unroll
        for (int jx = 0; jx < 4; jx++) {
            int pix = y * W + 4 * xt + jx;
            g_part[gp][pix][0] = m[jx];
            g_part[gp][pix][1] = s[jx];
            g_part[gp][pix][2] = sy[jx];
            g_part[gp][pix][3] = sx[jx];
        }
    }
}

// ---------------- K3: warp-per-pixel tree merge of 25 partials ----------------
// grid 504 x 256 threads: 8 warps/block, one pixel per warp.
__global__ __launch_bounds__(256) void offs_merge2_kernel() {
    int wid = threadIdx.x >> 5;
    int lane = threadIdx.x & 31;
    int pix = blockIdx.x * 8 + wid;      // 504*8 = 4032 exactly

    float m = -1e30f, s = 0.f, sy = 0.f, sx = 0.f;
    if (lane < 25) {
        float4 pm = *reinterpret_cast<const float4*>(&g_part[lane][pix][0]);
        m = pm.x; s = pm.y; sy = pm.z; sx = pm.w;
    }
#pragma unroll
    for (int o = 1; o <= 16; o <<= 1) {
        float m2 = __shfl_xor_sync(0xffffffffu, m, o);
        float s2 = __shfl_xor_sync(0xffffffffu, s, o);
        float sy2 = __shfl_xor_sync(0xffffffffu, sy, o);
        float sx2 = __shfl_xor_sync(0xffffffffu, sx, o);
        if (m2 > m) {
            float e = __expf(m - m2);
            s = s * e + s2; sy = sy * e + sy2; sx = sx * e + sx2; m = m2;
        } else {
            float e = __expf(m2 - m);
            s += s2 * e; sy += sy2 * e; sx += sx2 * e;
        }
    }
    if (lane == 0) {
        float inv = 1.f / s;
        g_off[pix][0] = 2.f * sy * inv;
        g_off[pix][1] = 2.f * sx * inv;
    }
}

// ---------------- K4: dil-1 correlations refs 1,2, register-tiled ----------------
// grid (48, 7, 2): (row y, a-pair, ref-1). 168 threads = 2 ap * 21 xt * 4 bt.
// Thread: 4 x-pixels (jx) * 4 b-offsets (jb), b = 4*bt+jb (store if b<13).
// shared idx for (jx,jb): (4xt+4bt) + jx + jb + 2  -> 12-float aligned window.
#define RSW4 104   // rs row width: max rbase0(92)+12 <= 104, 4-aligned
__global__ __launch_bounds__(168) void logits12b_kernel() {
    int y = blockIdx.x;
    int a0 = blockIdx.y * 2;
    int ref = blockIdx.z + 1;
    int tid = threadIdx.x;

    __shared__ float ts[32 * 84];          // [k][x]
    __shared__ float rs[2][32 * RSW4];     // [ap][k][xx+8], zero-padded

    int ap = tid / 84;                     // 0..1
    int rem = tid - ap * 84;
    int xt = rem >> 2;                     // 0..20
    int bt = rem & 3;                      // 0..3

    float acc[4][4];
#pragma unroll
    for (int i = 0; i < 4; i++)
#pragma unroll
        for (int j = 0; j < 4; j++) acc[i][j] = 0.f;

    const float4* tp = reinterpret_cast<const float4*>(g_tT + y * (W * C));

    for (int kc = 0; kc < 2; kc++) {
        // ts chunk
        for (int i = tid; i < 84 * 8; i += 168) {
            int x = i >> 3, f = i & 7;
            float4 v = tp[x * 16 + kc * 8 + f];
            int c4 = f << 2;
            ts[(c4 + 0) * 84 + x] = v.x;
            ts[(c4 + 1) * 84 + x] = v.y;
            ts[(c4 + 2) * 84 + x] = v.z;
            ts[(c4 + 3) * 84 + x] = v.w;
        }
        // rs chunks for both a rows
        for (int aa = 0; aa < 2; aa++) {
            int yy = y + (a0 + aa) - 6;
            bool rowok = (yy >= 0) && (yy < H);
            if (rowok) {
                // zero borders: cols [0,8) U [92,104) -> 20 cols per k-row
                for (int i = tid; i < 32 * 20; i += 168) {
                    int kk = i / 20, j = i - kk * 20;
                    int col = (j < 8) ? j : (84 + j);  // 8..19 -> 92..103
                    rs[aa][kk * RSW4 + col] = 0.f;
                }
                const float4* rp = reinterpret_cast<const float4*>(g_rT[ref] + yy * (W * C));
                for (int i = tid; i < 84 * 8; i += 168) {
                    int x = i >> 3, f = i & 7;
                    float4 v = rp[x * 16 + kc * 8 + f];
                    int c4 = f << 2;
                    rs[aa][(c4 + 0) * RSW4 + 8 + x] = v.x;
                    rs[aa][(c4 + 1) * RSW4 + 8 + x] = v.y;
                    rs[aa][(c4 + 2) * RSW4 + 8 + x] = v.z;
                    rs[aa][(c4 + 3) * RSW4 + 8 + x] = v.w;
                }
            } else {
                for (int i = tid; i < 32 * RSW4; i += 168) rs[aa][i] = 0.f;
            }
        }
        __syncthreads();

        int tbase = 4 * xt;
        int rbase0 = 4 * xt + 4 * bt;     // sh idx = rbase0 + jx + jb + 2
        const float* rsa = rs[ap];
#pragma unroll 4
        for (int k = 0; k < 32; k++) {
            float4 tq = *reinterpret_cast<const float4*>(ts + k * 84 + tbase);
            const float4* rr = reinterpret_cast<const float4*>(rsa + k * RSW4 + rbase0);
            float4 r0 = rr[0], r1 = rr[1], r2 = rr[2];
            float rv[12] = {r0.x,r0.y,r0.z,r0.w, r1.x,r1.y,r1.z,r1.w,
                            r2.x,r2.y,r2.z,r2.w};
            float tv[4] = {tq.x, tq.y, tq.z, tq.w};
#pragma unroll
            for (int jx = 0; jx < 4; jx++)
#pragma unroll
                for (int jb = 0; jb < 4; jb++)
                    acc[jx][jb] += tv[jx] * rv[jx + jb + 2];
        }
        __syncthreads();
    }

    int a = a0 + ap;
    if (a < 13) {
#pragma unroll
        for (int jx = 0; jx < 4; jx++) {
            int pix = y * W + 4 * xt + jx;
#pragma unroll
            for (int jb = 0; jb < 4; jb++) {
                int b = 4 * bt + jb;
                if (b < 13)
                    g_logits12[pix * 338 + (ref - 1) * 169 + a * 13 + b] = acc[jx][jb];
            }
        }
    }
}

// ---------------- K5: fused bilinear corr (ref0) + softmax(507) + output ----------------
// 512 threads/block, one pixel per block. 16 warps; D-dots computed by
// 16-lane half-warps (lane = 4 channels), reduce depth 4.
__global__ __launch_bounds__(512) void final3_kernel(float* __restrict__ out) {
    int pix = blockIdx.x;
    int y = pix / W;
    int x = pix - y * W;
    int tid = threadIdx.x;
    int wid = tid >> 5;          // 0..15
    int lane = tid & 31;
    int half = lane >> 4;        // 0/1
    int hl = lane & 15;          // 0..15

    __shared__ float lsh[507];
    __shared__ float Dsh[196];
    __shared__ float W0[196];
    __shared__ float red[16];
    __shared__ float oacc[16][32];

    // broadcast loads (all threads same address)
    float offy = g_off[pix][0];
    float offx = g_off[pix][1];
    float Yf = (float)y + offy;
    float Xf = (float)x + offx;
    float fYf = floorf(Yf), fXf = floorf(Xf);
    int fy = (int)fYf, fx = (int)fXf;
    float wy = Yf - fYf, wx = Xf - fXf;
    float c00 = (1.f - wy) * (1.f - wx);
    float c01 = (1.f - wy) * wx;
    float c10 = wy * (1.f - wx);
    float c11 = wy * wx;

    // t features: each lane holds 4 channels (same for both halves)
    float4 t4 = reinterpret_cast<const float4*>(g_tT + pix * C)[hl];

    // refs 1,2 logits (coalesced, pixel-major): one element per thread
    if (tid < 338) lsh[169 + tid] = g_logits12[pix * 338 + tid];

    // 14x14 integer-grid dot field: half-warp per dot, lane = 4 channels
    for (int d0 = 2 * wid; d0 < 196; d0 += 32) {
        int d = d0 + half;
        int aa = d / 14, bb = d - aa * 14;
        int ry = fy + aa - 6, rx = fx + bb - 6;
        float v = 0.f;
        if ((unsigned)ry < (unsigned)H && (unsigned)rx < (unsigned)W) {
            float4 r4 = reinterpret_cast<const float4*>(g_rT[0] + (ry * W + rx) * C)[hl];
            v = t4.x * r4.x + t4.y * r4.y + t4.z * r4.z + t4.w * r4.w;
        }
#pragma unroll
        for (int o = 1; o <= 8; o <<= 1) v += __shfl_xor_sync(0xffffffffu, v, o);
        if (hl == 0) Dsh[d] = v;
    }
    __syncthreads();

    // ref0 logits via shared bilinear fractions
    if (tid < 169) {
        int p = tid / 13, q = tid - p * 13;
        lsh[tid] = c00 * Dsh[p * 14 + q] + c01 * Dsh[p * 14 + q + 1]
                 + c10 * Dsh[(p + 1) * 14 + q] + c11 * Dsh[(p + 1) * 14 + q + 1];
    }
    __syncthreads();

    // block softmax over 507 logits (one element per thread)
    float lm = (tid < 507) ? lsh[tid] : -1e30f;
#pragma unroll
    for (int o = 16; o; o >>= 1) lm = fmaxf(lm, __shfl_xor_sync(0xffffffffu, lm, o));
    if (lane == 0) red[wid] = lm;
    __syncthreads();
    float M = red[0];
#pragma unroll
    for (int i = 1; i < 16; i++) M = fmaxf(M, red[i]);
    __syncthreads();

    float ls = 0.f;
    if (tid < 507) {
        float e = __expf(lsh[tid] - M);
        lsh[tid] = e;
        ls = e;
    }
#pragma unroll
    for (int o = 16; o; o >>= 1) ls += __shfl_xor_sync(0xffffffffu, ls, o);
    if (lane == 0) red[wid] = ls;
    __syncthreads();
    float S = 0.f;
#pragma unroll
    for (int i = 0; i < 16; i++) S += red[i];
    float invS = 1.f / S;

    // combined integer-grid weights for ref0 output gather
    if (tid < 196) {
        int aa = tid / 14, bb = tid - aa * 14;
        float w00 = (aa < 13 && bb < 13) ? lsh[aa * 13 + bb] : 0.f;
        float w01 = (aa < 13 && bb >= 1) ? lsh[aa * 13 + bb - 1] : 0.f;
        float w10 = (aa >= 1 && bb < 13) ? lsh[(aa - 1) * 13 + bb] : 0.f;
        float w11 = (aa >= 1 && bb >= 1) ? lsh[(aa - 1) * 13 + bb - 1] : 0.f;
        W0[tid] = c00 * w00 + c01 * w01 + c10 * w10 + c11 * w11;
    }
    __syncthreads();

    // gather: warp-per-sample, lane = channel, coalesced 128B loads
    float acc = 0.f;
    for (int s = wid; s < 534; s += 16) {
        float wgt;
        int ry, rx;
        const float* src;
        if (s < 196) {
            int aa = s / 14, bb = s - aa * 14;
            wgt = W0[s];
            ry = fy + aa - 6; rx = fx + bb - 6;
            src = g_qrT[0];
        } else if (s < 365) {
            int n = s - 196;
            int p = n / 13, q = n - p * 13;
            wgt = lsh[169 + n];
            ry = y + p - 6; rx = x + q - 6;
            src = g_qrT[1];
        } else {
            int n = s - 365;
            int p = n / 13, q = n - p * 13;
            wgt = lsh[338 + n];
            ry = y + p - 6; rx = x + q - 6;
            src = g_qrT[2];
        }
        if ((unsigned)ry < (unsigned)H && (unsigned)rx < (unsigned)W)
            acc += wgt * src[(ry * W + rx) * CQ + lane];
    }
    oacc[wid][lane] = acc;
    __syncthreads();
    if (tid < 32) {
        float t = 0.f;
#pragma unroll
        for (int wrp = 0; wrp < 16; wrp++) t += oacc[wrp][tid];
        out[tid * HW + pix] = t * invS;
    }
}

// ---------------- launch ----------------
extern "C" void kernel_launch(void* const* d_in, const int* in_sizes, int n_in,
                              void* d_out, int out_size) {
    const float* fr = (const float*)d_in[0];
    const float* ft = (const float*)d_in[1];
    const float* qz = (const float*)d_in[2];
    float* out = (float*)d_out;

    prep_feats_kernel<<<dim3(126, 2, 4), dim3(32, 8)>>>(fr, ft);
    prep_qr_kernel<<<256, 256>>>(qz);
    offs2_kernel<<<dim3(48, 25), 96>>>();
    offs_merge2_kernel<<<504, 256>>>();
    logits12b_kernel<<<dim3(48, 7, 2), 168>>>();
    final3_kernel<<<HW, 512>>>(out);
}